// round 12
// baseline (speedup 1.0000x reference)
#include <cuda_runtime.h>
#include <cuda_bf16.h>
#include <cuda_fp16.h>
#include <cstdint>
#include <math.h>

// VectorQuantizer N=65536, D=64, K=512.
// R12: SINGLE-phase HMMA screen with per-thread smem candidate buffers
// (halves screening GEMM vs R10/R11's two-phase) + exact fp32 rescore.
// d_out: [0]=loss, [1..ND]=q_st, [1+ND]=ppl, [2+ND..)=idx.

#define D_DIM   64
#define K_CODES 512
#define M_TILE  128
#define TILES   512          // 65536 / 128
#define TPB     256
#define EPS     5e-3f        // >= 2x two-sided worst-case bf16 screen error
#define MAXC    24           // per-thread buffer slots (covers 2 rows)

typedef unsigned int u32;
typedef unsigned long long u64;

__device__ __nv_bfloat16 g_cbb[K_CODES * D_DIM];  // bf16 codebook
__device__ float  g_cnorm[K_CODES];
__device__ int    g_hist[K_CODES];                // reset by vq_final
__device__ double g_sse;                          // reset by vq_final

__device__ __forceinline__ u32 smem_u32(const void* p) {
    u32 a;
    asm("{ .reg .u64 t; cvta.to.shared.u64 t, %1; cvt.u32.u64 %0, t; }"
        : "=r"(a) : "l"(p));
    return a;
}
__device__ __forceinline__ u32 sw128(u32 b) { return b ^ ((b >> 3) & 0x70); }

__device__ __forceinline__ void ldsm_x4(u32& r0, u32& r1, u32& r2, u32& r3, u32 a) {
    asm volatile("ldmatrix.sync.aligned.m8n8.x4.shared.b16 {%0,%1,%2,%3}, [%4];"
                 : "=r"(r0), "=r"(r1), "=r"(r2), "=r"(r3) : "r"(a));
}
__device__ __forceinline__ void ldsm_x2(u32& r0, u32& r1, u32 a) {
    asm volatile("ldmatrix.sync.aligned.m8n8.x2.shared.b16 {%0,%1}, [%2];"
                 : "=r"(r0), "=r"(r1) : "r"(a));
}
__device__ __forceinline__ void mma16816(float& c0, float& c1, float& c2, float& c3,
                                         u32 a0, u32 a1, u32 a2, u32 a3,
                                         u32 b0, u32 b1) {
    asm volatile(
        "mma.sync.aligned.m16n8k16.row.col.f32.bf16.bf16.f32 "
        "{%0,%1,%2,%3}, {%4,%5,%6,%7}, {%8,%9}, {%0,%1,%2,%3};"
        : "+f"(c0), "+f"(c1), "+f"(c2), "+f"(c3)
        : "r"(a0), "r"(a1), "r"(a2), "r"(a3), "r"(b0), "r"(b1));
}

// Pack candidate: bit31 = row-in-pair, bits[16:31) = k, bits[0:16) = f16_rd(t)
__device__ __forceinline__ u32 pack_cand(int rbit, int k, float t) {
    u32 h = (u32)__half_as_ushort(__float2half_rd(t));
    return ((u32)rbit << 31) | ((u32)k << 16) | h;
}

// ---- smem layout (bytes), ~108 KB -> 2 CTAs/SM ----
#define SM_A    0                        // 128 rows * 128B bf16 (SW128) = 16384
#define SM_B    16384                    // 512 rows * 128B bf16 (SW128) = 65536
#define SM_CN   81920                    // 512 f32 = 2048
#define SM_AN   83968                    // 128 f32 = 512
#define SM_CNT  84480                    // 128 int (overflow flags) = 512
#define SM_KEY  84992                    // 128 u64 = 1024
#define SM_RED  86016                    // 8 double = 64
#define SM_CBUF 86080                    // 256*24 u32 = 24576 (reused: AND)
#define SM_AND  SM_CBUF                  // 256 double half-norms (pre-screen)
#define SMEM_SZ 110656

// ---------------------------------------------------------------------------
__global__ void vq_prep(const float* __restrict__ cb) {
    int gt = blockIdx.x * 256 + threadIdx.x;
    int w = gt >> 5, lane = gt & 31;                 // w = code 0..511
    const float* c = cb + w * D_DIM;
    float v0 = c[lane], v1 = c[lane + 32];
    g_cbb[w * D_DIM + lane]      = __float2bfloat16(v0);
    g_cbb[w * D_DIM + lane + 32] = __float2bfloat16(v1);
    double s = (double)__fmul_rn(v0, v0) + (double)__fmul_rn(v1, v1);
#pragma unroll
    for (int o = 16; o > 0; o >>= 1)
        s += __shfl_xor_sync(0xFFFFFFFFu, s, o);
    if (lane == 0) g_cnorm[w] = (float)s;
}

// Exact fp32 score s = fl( fl(A - 2*dot) + C ), 4-chain fp32 dot.
__device__ __forceinline__ float exact_score(const float* __restrict__ cb,
                                             const float4* __restrict__ xr,
                                             float A, float C, int k) {
    const float4* cr = (const float4*)(cb + k * D_DIM);
    float a0 = 0.f, a1 = 0.f, a2 = 0.f, a3 = 0.f;
#pragma unroll
    for (int j = 0; j < D_DIM / 4; j++) {
        float4 cv = cr[j], xv = xr[j];
        a0 = __fmaf_rn(xv.x, cv.x, a0);
        a1 = __fmaf_rn(xv.y, cv.y, a1);
        a2 = __fmaf_rn(xv.z, cv.z, a2);
        a3 = __fmaf_rn(xv.w, cv.w, a3);
    }
    float dot = (a0 + a1) + (a2 + a3);
    return __fadd_rn(__fmaf_rn(-2.f, dot, A), C);
}

// ---------------------------------------------------------------------------
__global__ __launch_bounds__(TPB, 2)
void vq_main(const float* __restrict__ x, const float* __restrict__ cb,
             float* __restrict__ outq, float* __restrict__ outidx) {
    extern __shared__ char smem[];
    const u32 sb  = smem_u32(smem);
    const int tid = threadIdx.x;
    const int lane = tid & 31;
    const int wrow = (tid >> 5) * 16;               // warp's first local row
    const int row  = tid & 127;                     // pair row
    const int half = tid >> 7;                      // 0: cols 0-31, 1: 32-63

    float*  scn  = (float*)(smem + SM_CN);
    float*  san  = (float*)(smem + SM_AN);
    double* sand = (double*)(smem + SM_AND);
    int*    sflag= (int*)(smem + SM_CNT);
    u32*    scbuf= (u32*)(smem + SM_CBUF);
    u64*    skey = (u64*)(smem + SM_KEY);
    double* sred = (double*)(smem + SM_RED);

    // B: bf16 codebook -> smem SW128 (2 rows/thread, 8x uint4 each)
    {
#pragma unroll
        for (int rr = 0; rr < 2; rr++) {
            int r = tid * 2 + rr;
            const uint4* src = (const uint4*)(g_cbb + r * D_DIM);
#pragma unroll
            for (int j = 0; j < 8; j++)
                *(uint4*)(smem + SM_B + sw128(r * 128 + j * 16)) = src[j];
        }
    }
    scn[tid]       = g_cnorm[tid];
    scn[tid + 256] = g_cnorm[tid + 256];
    if (tid < M_TILE) { sflag[tid] = 0; skey[tid] = ~0ull; }

    // A: convert x half-rows to bf16 SW128 + half norms (all 256 threads)
    {
        const float4* gx = (const float4*)(x +
            ((size_t)blockIdx.x * M_TILE + row) * D_DIM + half * 32);
        double sa = 0.0;
#pragma unroll
        for (int j = 0; j < 8; j++) {
            float4 v = gx[j];
            sa += (double)__fmul_rn(v.x, v.x); sa += (double)__fmul_rn(v.y, v.y);
            sa += (double)__fmul_rn(v.z, v.z); sa += (double)__fmul_rn(v.w, v.w);
            __nv_bfloat162 p0 = __floats2bfloat162_rn(v.x, v.y);
            __nv_bfloat162 p1 = __floats2bfloat162_rn(v.z, v.w);
            u32 base = (u32)row * 128 + half * 64 + j * 8;
            *(u32*)(smem + SM_A + sw128(base))     = *(u32*)&p0;
            *(u32*)(smem + SM_A + sw128(base + 4)) = *(u32*)&p1;
        }
        sand[tid] = sa;
    }
    __syncthreads();
    if (tid < M_TILE) san[tid] = (float)(sand[tid] + sand[tid + 128]);
    __syncthreads();   // sand (=CBUF region) free after this point

    // ---- SINGLE-phase screen: warp rows [wrow, wrow+16) x 512 codes ----
    const int r0 = wrow + (lane >> 2);
    float thr0, thr1;
    int nc = 0;
    {
        u32 af[4][4];
        {
            int r  = (lane & 7) + ((lane & 8) ? 8 : 0);
            int hh = (lane >> 4) & 1;
            u32 abase = (u32)(wrow + r) * 128 + hh * 16;
#pragma unroll
            for (int ks = 0; ks < 4; ks++)
                ldsm_x4(af[ks][0], af[ks][1], af[ks][2], af[ks][3],
                        sb + SM_A + sw128(abase + ks * 32));
        }
        const u32 bbase = (u32)(lane & 7) * 128 + ((lane >> 3) & 1) * 16;
        const int nlo = (lane & 3) * 2;
        u32* mybuf = scbuf + tid * MAXC;

        // Private running row bests; pushes vs private best + EPS.
        // Containment: private_tb >= rowmin, so any k with t < rowmin+EPS
        // is pushed by its owning thread. Final filter uses the true rowmin.
        float tb0 = 3.4e38f, tb1 = 3.4e38f;
#pragma unroll 4
        for (int tile = 0; tile < 64; tile++) {
            float c0 = 0.f, c1 = 0.f, c2 = 0.f, c3 = 0.f;
            u32 tb_off = (u32)tile * 8 * 128;
#pragma unroll
            for (int ks = 0; ks < 4; ks++) {
                u32 b0, b1;
                ldsm_x2(b0, b1, sb + SM_B + sw128(tb_off + bbase + ks * 32));
                mma16816(c0, c1, c2, c3,
                         af[ks][0], af[ks][1], af[ks][2], af[ks][3], b0, b1);
            }
            int k0 = tile * 8 + nlo;
            float cn0 = scn[k0], cn1 = scn[k0 + 1];
            float t00 = __fmaf_rn(-2.f, c0, cn0);
            float t01 = __fmaf_rn(-2.f, c1, cn1);
            float t10 = __fmaf_rn(-2.f, c2, cn0);
            float t11 = __fmaf_rn(-2.f, c3, cn1);
            if (t00 < tb0 + EPS) {
                if (nc < MAXC) mybuf[nc] = pack_cand(0, k0, t00);
                nc++;
            }
            tb0 = fminf(tb0, t00);
            if (t01 < tb0 + EPS) {
                if (nc < MAXC) mybuf[nc] = pack_cand(0, k0 + 1, t01);
                nc++;
            }
            tb0 = fminf(tb0, t01);
            if (t10 < tb1 + EPS) {
                if (nc < MAXC) mybuf[nc] = pack_cand(1, k0, t10);
                nc++;
            }
            tb1 = fminf(tb1, t10);
            if (t11 < tb1 + EPS) {
                if (nc < MAXC) mybuf[nc] = pack_cand(1, k0 + 1, t11);
                nc++;
            }
            tb1 = fminf(tb1, t11);
        }
        // True row minima via quad reduce -> final thresholds
        tb0 = fminf(tb0, __shfl_xor_sync(0xFFFFFFFFu, tb0, 1));
        tb0 = fminf(tb0, __shfl_xor_sync(0xFFFFFFFFu, tb0, 2));
        tb1 = fminf(tb1, __shfl_xor_sync(0xFFFFFFFFu, tb1, 1));
        tb1 = fminf(tb1, __shfl_xor_sync(0xFFFFFFFFu, tb1, 2));
        thr0 = tb0 + EPS;
        thr1 = tb1 + EPS;

        if (nc > MAXC) {                 // rare (~0.2%): flag both rows
            sflag[r0] = 1;
            sflag[r0 + 8] = 1;
        }
    }
    __syncthreads();

    // ---- exact rescore of filtered candidates (screen-thread-owned) ----
    {
        const u32* mybuf = scbuf + tid * MAXC;
        int m = nc < MAXC ? nc : MAXC;
        for (int i = 0; i < m; i++) {
            u32 p = mybuf[i];
            int rbit = (int)(p >> 31);
            int k = (int)((p >> 16) & 0x7FFF);
            float t16 = __half2float(__ushort_as_half((unsigned short)(p & 0xFFFF)));
            int rw = rbit ? r0 + 8 : r0;
            float thr = rbit ? thr1 : thr0;
            // f16_rd(t) <= t, so t < thr implies t16 < thr: no true cand lost.
            if (t16 < thr && !sflag[rw]) {
                int v = blockIdx.x * M_TILE + rw;
                const float4* xr = (const float4*)(x + (size_t)v * D_DIM);
                float s = exact_score(cb, xr, san[rw], scn[k], k);
                // s > 0 (dist^2 ~ 64): float-bits order == value order.
                atomicMin(&skey[rw], ((u64)__float_as_uint(s) << 32) | (u32)k);
            }
        }
    }
    // Flagged rows: pair-split full exact scan (astronomically rare)
    if (sflag[row]) {
        const float4* xr = (const float4*)(x +
            ((size_t)blockIdx.x * M_TILE + row) * D_DIM);
        for (int k = half; k < K_CODES; k += 2) {
            float s = exact_score(cb, xr, san[row], scn[k], k);
            atomicMin(&skey[row], ((u64)__float_as_uint(s) << 32) | (u32)k);
        }
    }
    __syncthreads();

    // ---- outputs: 2 threads/row ----
    const int vid = blockIdx.x * M_TILE + row;
    const int bi = (int)(u32)skey[row];
    if (half == 0) {
        outidx[vid] = (float)bi;
        atomicAdd(&g_hist[bi], 1);
    }

    // quantized_st = x + (q - x); SSE of (q - x)^2.
    // outq is d_out+1 (odd float offset): scalar 32-bit stores only.
    float sse = 0.f;
    {
        const float4* qr = (const float4*)(cb + bi * D_DIM) + half * 8;
        const float4* xh = (const float4*)(x + (size_t)vid * D_DIM) + half * 8;
        float* o = outq + (size_t)vid * D_DIM + half * 32;
#pragma unroll
        for (int j = 0; j < 8; j++) {
            float4 qv = qr[j], xv = xh[j];
            float d0 = __fadd_rn(qv.x, -xv.x), d1 = __fadd_rn(qv.y, -xv.y);
            float d2 = __fadd_rn(qv.z, -xv.z), d3 = __fadd_rn(qv.w, -xv.w);
            sse += d0 * d0 + d1 * d1 + d2 * d2 + d3 * d3;
            o[4 * j]     = __fadd_rn(xv.x, d0);
            o[4 * j + 1] = __fadd_rn(xv.y, d1);
            o[4 * j + 2] = __fadd_rn(xv.z, d2);
            o[4 * j + 3] = __fadd_rn(xv.w, d3);
        }
    }

    // Block-reduce SSE -> one double atomic per CTA
#pragma unroll
    for (int o = 16; o > 0; o >>= 1)
        sse += __shfl_xor_sync(0xFFFFFFFFu, sse, o);
    if ((tid & 31) == 0) sred[tid >> 5] = (double)sse;
    __syncthreads();
    if (tid == 0) {
        double s = 0.0;
#pragma unroll
        for (int w = 0; w < 8; w++) s += sred[w];
        atomicAdd(&g_sse, s);
    }
}

// ---------------------------------------------------------------------------
__global__ void vq_final(float* __restrict__ out, int nd, int n) {
    int t = threadIdx.x;  // 512
    __shared__ double ssum;
    __shared__ float red[16];

    int h = g_hist[t];
    g_hist[t] = 0;                         // reset for next replay
    if (t == 0) { ssum = g_sse; g_sse = 0.0; }

    float p = (float)h / (float)n;
    float e = p * logf(p + 1e-10f);
#pragma unroll
    for (int o = 16; o > 0; o >>= 1)
        e += __shfl_xor_sync(0xFFFFFFFFu, e, o);
    if ((t & 31) == 0) red[t >> 5] = e;
    __syncthreads();
    if (t < 16) {
        float v = red[t];
#pragma unroll
        for (int o = 8; o > 0; o >>= 1)
            v += __shfl_xor_sync(0xFFFFu, v, o);
        if (t == 0) {
            out[1 + nd] = expf(-v);
            float m = (float)(ssum / (double)nd);
            out[0] = m + 0.25f * m;
        }
    }
}

// ---------------------------------------------------------------------------
extern "C" void kernel_launch(void* const* d_in, const int* in_sizes, int n_in,
                              void* d_out, int out_size) {
    const float* x  = (const float*)d_in[0];
    const float* cb = (const float*)d_in[1];
    float* out = (float*)d_out;

    int nd = in_sizes[0];   // 4194304
    int n  = nd / D_DIM;    // 65536

    cudaFuncSetAttribute(vq_main, cudaFuncAttributeMaxDynamicSharedMemorySize,
                         SMEM_SZ);

    vq_prep<<<64, 256>>>(cb);
    vq_main<<<TILES, TPB, SMEM_SZ>>>(x, cb, out + 1, out + 2 + nd);
    vq_final<<<1, K_CODES>>>(out, nd, n);
}

// round 13
// speedup vs baseline: 2.2865x; 2.2865x over previous
#include <cuda_runtime.h>
#include <cuda_bf16.h>
#include <cuda_fp16.h>
#include <cstdint>
#include <math.h>

// VectorQuantizer N=65536, D=64, K=512.
// R13: SINGLE MMA screen pass, branch-free; per-thread per-tile f16 minima in
// registers -> 64-bit flagged-tile mask -> direct exact fp32 rescore of the
// ~2 flagged tiles/thread (no candidate lists, no phase-2 MMA, no fallback).
// d_out: [0]=loss, [1..ND]=q_st, [1+ND]=ppl, [2+ND..)=idx.

#define D_DIM   64
#define K_CODES 512
#define M_TILE  128
#define TILES   512          // 65536 / 128
#define TPB     256
#define EPS     5e-3f        // >= 2x two-sided worst-case bf16 screen error

typedef unsigned int u32;
typedef unsigned long long u64;

__device__ __nv_bfloat16 g_cbb[K_CODES * D_DIM];  // bf16 codebook
__device__ float  g_cnorm[K_CODES];
__device__ int    g_hist[K_CODES];                // reset by vq_final
__device__ double g_sse;                          // reset by vq_final

__device__ __forceinline__ u32 smem_u32(const void* p) {
    u32 a;
    asm("{ .reg .u64 t; cvta.to.shared.u64 t, %1; cvt.u32.u64 %0, t; }"
        : "=r"(a) : "l"(p));
    return a;
}
__device__ __forceinline__ u32 sw128(u32 b) { return b ^ ((b >> 3) & 0x70); }

__device__ __forceinline__ void ldsm_x4(u32& r0, u32& r1, u32& r2, u32& r3, u32 a) {
    asm volatile("ldmatrix.sync.aligned.m8n8.x4.shared.b16 {%0,%1,%2,%3}, [%4];"
                 : "=r"(r0), "=r"(r1), "=r"(r2), "=r"(r3) : "r"(a));
}
__device__ __forceinline__ void ldsm_x2(u32& r0, u32& r1, u32 a) {
    asm volatile("ldmatrix.sync.aligned.m8n8.x2.shared.b16 {%0,%1}, [%2];"
                 : "=r"(r0), "=r"(r1) : "r"(a));
}
__device__ __forceinline__ void mma16816(float& c0, float& c1, float& c2, float& c3,
                                         u32 a0, u32 a1, u32 a2, u32 a3,
                                         u32 b0, u32 b1) {
    asm volatile(
        "mma.sync.aligned.m16n8k16.row.col.f32.bf16.bf16.f32 "
        "{%0,%1,%2,%3}, {%4,%5,%6,%7}, {%8,%9}, {%0,%1,%2,%3};"
        : "+f"(c0), "+f"(c1), "+f"(c2), "+f"(c3)
        : "r"(a0), "r"(a1), "r"(a2), "r"(a3), "r"(b0), "r"(b1));
}

// ---- smem layout (bytes), ~88 KB -> 2 CTAs/SM ----
#define SM_A    0                        // 128 rows * 128B bf16 (SW128) = 16384
#define SM_B    16384                    // 512 rows * 128B bf16 (SW128) = 65536
#define SM_CN   81920                    // 512 f32 = 2048
#define SM_AN   83968                    // 128 f32 = 512
#define SM_AND  84480                    // 256 double (half norms) = 2048
#define SM_KEY  86528                    // 128 u64 = 1024
#define SM_RED  87552                    // 8 double = 64
#define SMEM_SZ 87616

// ---------------------------------------------------------------------------
__global__ void vq_prep(const float* __restrict__ cb) {
    int gt = blockIdx.x * 256 + threadIdx.x;
    int w = gt >> 5, lane = gt & 31;                 // w = code 0..511
    const float* c = cb + w * D_DIM;
    float v0 = c[lane], v1 = c[lane + 32];
    g_cbb[w * D_DIM + lane]      = __float2bfloat16(v0);
    g_cbb[w * D_DIM + lane + 32] = __float2bfloat16(v1);
    double s = (double)__fmul_rn(v0, v0) + (double)__fmul_rn(v1, v1);
#pragma unroll
    for (int o = 16; o > 0; o >>= 1)
        s += __shfl_xor_sync(0xFFFFFFFFu, s, o);
    if (lane == 0) g_cnorm[w] = (float)s;
}

// Exact fp32 score s = fl( fl(A - 2*dot) + C ), 4-chain fp32 dot.
__device__ __forceinline__ float exact_score(const float* __restrict__ cb,
                                             const float4* __restrict__ xr,
                                             float A, float C, int k) {
    const float4* cr = (const float4*)(cb + k * D_DIM);
    float a0 = 0.f, a1 = 0.f, a2 = 0.f, a3 = 0.f;
#pragma unroll
    for (int j = 0; j < D_DIM / 4; j++) {
        float4 cv = cr[j], xv = xr[j];
        a0 = __fmaf_rn(xv.x, cv.x, a0);
        a1 = __fmaf_rn(xv.y, cv.y, a1);
        a2 = __fmaf_rn(xv.z, cv.z, a2);
        a3 = __fmaf_rn(xv.w, cv.w, a3);
    }
    float dot = (a0 + a1) + (a2 + a3);
    return __fadd_rn(__fmaf_rn(-2.f, dot, A), C);
}

// ---------------------------------------------------------------------------
__global__ __launch_bounds__(TPB, 2)
void vq_main(const float* __restrict__ x, const float* __restrict__ cb,
             float* __restrict__ outq, float* __restrict__ outidx) {
    extern __shared__ char smem[];
    const u32 sb  = smem_u32(smem);
    const int tid = threadIdx.x;
    const int lane = tid & 31;
    const int wrow = (tid >> 5) * 16;               // warp's first local row
    const int row  = tid & 127;                     // pair row
    const int half = tid >> 7;                      // 0: cols 0-31, 1: 32-63

    float*  scn  = (float*)(smem + SM_CN);
    float*  san  = (float*)(smem + SM_AN);
    double* sand = (double*)(smem + SM_AND);
    u64*    skey = (u64*)(smem + SM_KEY);
    double* sred = (double*)(smem + SM_RED);

    // B: bf16 codebook -> smem SW128 (2 rows/thread, 8x uint4 each)
    {
#pragma unroll
        for (int rr = 0; rr < 2; rr++) {
            int r = tid * 2 + rr;
            const uint4* src = (const uint4*)(g_cbb + r * D_DIM);
#pragma unroll
            for (int j = 0; j < 8; j++)
                *(uint4*)(smem + SM_B + sw128(r * 128 + j * 16)) = src[j];
        }
    }
    scn[tid]       = g_cnorm[tid];
    scn[tid + 256] = g_cnorm[tid + 256];
    if (tid < M_TILE) skey[tid] = ~0ull;

    // A: convert x half-rows to bf16 SW128 + half norms (all 256 threads)
    {
        const float4* gx = (const float4*)(x +
            ((size_t)blockIdx.x * M_TILE + row) * D_DIM + half * 32);
        double sa = 0.0;
#pragma unroll
        for (int j = 0; j < 8; j++) {
            float4 v = gx[j];
            sa += (double)__fmul_rn(v.x, v.x); sa += (double)__fmul_rn(v.y, v.y);
            sa += (double)__fmul_rn(v.z, v.z); sa += (double)__fmul_rn(v.w, v.w);
            __nv_bfloat162 p0 = __floats2bfloat162_rn(v.x, v.y);
            __nv_bfloat162 p1 = __floats2bfloat162_rn(v.z, v.w);
            u32 base = (u32)row * 128 + half * 64 + j * 8;
            *(u32*)(smem + SM_A + sw128(base))     = *(u32*)&p0;
            *(u32*)(smem + SM_A + sw128(base + 4)) = *(u32*)&p1;
        }
        sand[tid] = sa;
    }
    __syncthreads();
    if (tid < M_TILE) san[tid] = (float)(sand[tid] + sand[tid + 128]);
    __syncthreads();

    // ---- SINGLE screen pass: warp rows [wrow, wrow+16) x 512 codes ----
    // Branch-free mainloop; per-thread per-tile f16 minima packed in regs.
    const int r0 = wrow + (lane >> 2);
    const int nlo = (lane & 3) * 2;
    u32 tmins[32];                                  // 64 tiles, 2 f16 per u32
    float tb0 = 3.4e38f, tb1 = 3.4e38f;
    {
        u32 af[4][4];
        {
            int r  = (lane & 7) + ((lane & 8) ? 8 : 0);
            int hh = (lane >> 4) & 1;
            u32 abase = (u32)(wrow + r) * 128 + hh * 16;
#pragma unroll
            for (int ks = 0; ks < 4; ks++)
                ldsm_x4(af[ks][0], af[ks][1], af[ks][2], af[ks][3],
                        sb + SM_A + sw128(abase + ks * 32));
        }
        const u32 bbase = (u32)(lane & 7) * 128 + ((lane >> 3) & 1) * 16;

#pragma unroll
        for (int tp = 0; tp < 32; tp++) {
            u32 hpack = 0;
#pragma unroll
            for (int sub = 0; sub < 2; sub++) {
                const int tile = 2 * tp + sub;
                float c0 = 0.f, c1 = 0.f, c2 = 0.f, c3 = 0.f;
                u32 tb_off = (u32)tile * 8 * 128;
#pragma unroll
                for (int ks = 0; ks < 4; ks++) {
                    u32 b0, b1;
                    ldsm_x2(b0, b1, sb + SM_B + sw128(tb_off + bbase + ks * 32));
                    mma16816(c0, c1, c2, c3,
                             af[ks][0], af[ks][1], af[ks][2], af[ks][3], b0, b1);
                }
                int k0 = tile * 8 + nlo;
                float cn0 = scn[k0], cn1 = scn[k0 + 1];
                float t00 = __fmaf_rn(-2.f, c0, cn0);
                float t01 = __fmaf_rn(-2.f, c1, cn1);
                float t10 = __fmaf_rn(-2.f, c2, cn0);
                float t11 = __fmaf_rn(-2.f, c3, cn1);
                tb0 = fminf(tb0, fminf(t00, t01));
                tb1 = fminf(tb1, fminf(t10, t11));
                float tm = fminf(fminf(t00, t01), fminf(t10, t11));
                u32 h = (u32)__half_as_ushort(__float2half_rd(tm));
                hpack |= h << (16 * sub);
            }
            tmins[tp] = hpack;
        }
    }
    // True row minima via quad reduce -> thresholds
    tb0 = fminf(tb0, __shfl_xor_sync(0xFFFFFFFFu, tb0, 1));
    tb0 = fminf(tb0, __shfl_xor_sync(0xFFFFFFFFu, tb0, 2));
    tb1 = fminf(tb1, __shfl_xor_sync(0xFFFFFFFFu, tb1, 1));
    tb1 = fminf(tb1, __shfl_xor_sync(0xFFFFFFFFu, tb1, 2));
    const float thr0 = tb0 + EPS, thr1 = tb1 + EPS;
    const float thrm = fmaxf(thr0, thr1);

    // Flagged-tile mask (branch-free). f16_rd(min) <= min, so every tile
    // containing a sub-threshold score is flagged (containment-safe).
    u64 mask = 0;
#pragma unroll
    for (int tp = 0; tp < 32; tp++) {
        u32 pk = tmins[tp];
        float lo = __half2float(__ushort_as_half((unsigned short)(pk & 0xFFFF)));
        float hi = __half2float(__ushort_as_half((unsigned short)(pk >> 16)));
        mask |= ((u64)(lo < thrm) << (2 * tp)) | ((u64)(hi < thrm) << (2 * tp + 1));
    }

    // Direct exact rescore of flagged tiles (~2/thread): 4 scores each.
    // Above-threshold extras are harmless (can't beat the contained argmin;
    // key packs k so equal scores resolve to lowest index = jnp.argmin).
    {
        const int vidA = blockIdx.x * M_TILE + r0;
        const float4* xrA = (const float4*)(x + (size_t)vidA * D_DIM);
        const float4* xrB = (const float4*)(x + (size_t)(vidA + 8) * D_DIM);
        const float AA = san[r0], AB = san[r0 + 8];
        while (mask) {
            int tile = __ffsll((long long)mask) - 1;
            mask &= mask - 1;
            int k0 = tile * 8 + nlo;
            float cn0 = scn[k0], cn1 = scn[k0 + 1];
            float s00 = exact_score(cb, xrA, AA, cn0, k0);
            float s01 = exact_score(cb, xrA, AA, cn1, k0 + 1);
            float s10 = exact_score(cb, xrB, AB, cn0, k0);
            float s11 = exact_score(cb, xrB, AB, cn1, k0 + 1);
            // s > 0 (dist^2 ~ 64): float-bits order == value order.
            u64 kA = min(((u64)__float_as_uint(s00) << 32) | (u32)k0,
                         ((u64)__float_as_uint(s01) << 32) | (u32)(k0 + 1));
            u64 kB = min(((u64)__float_as_uint(s10) << 32) | (u32)k0,
                         ((u64)__float_as_uint(s11) << 32) | (u32)(k0 + 1));
            atomicMin(&skey[r0], kA);
            atomicMin(&skey[r0 + 8], kB);
        }
    }
    __syncthreads();

    // ---- outputs: 2 threads/row ----
    const int vid = blockIdx.x * M_TILE + row;
    const int bi = (int)(u32)skey[row];
    if (half == 0) {
        outidx[vid] = (float)bi;
        atomicAdd(&g_hist[bi], 1);
    }

    // quantized_st = x + (q - x); SSE of (q - x)^2.
    // outq is d_out+1 (odd float offset): scalar 32-bit stores only.
    float sse = 0.f;
    {
        const float4* qr = (const float4*)(cb + bi * D_DIM) + half * 8;
        const float4* xh = (const float4*)(x + (size_t)vid * D_DIM) + half * 8;
        float* o = outq + (size_t)vid * D_DIM + half * 32;
#pragma unroll
        for (int j = 0; j < 8; j++) {
            float4 qv = qr[j], xv = xh[j];
            float d0 = __fadd_rn(qv.x, -xv.x), d1 = __fadd_rn(qv.y, -xv.y);
            float d2 = __fadd_rn(qv.z, -xv.z), d3 = __fadd_rn(qv.w, -xv.w);
            sse += d0 * d0 + d1 * d1 + d2 * d2 + d3 * d3;
            o[4 * j]     = __fadd_rn(xv.x, d0);
            o[4 * j + 1] = __fadd_rn(xv.y, d1);
            o[4 * j + 2] = __fadd_rn(xv.z, d2);
            o[4 * j + 3] = __fadd_rn(xv.w, d3);
        }
    }

    // Block-reduce SSE -> one double atomic per CTA
#pragma unroll
    for (int o = 16; o > 0; o >>= 1)
        sse += __shfl_xor_sync(0xFFFFFFFFu, sse, o);
    if ((tid & 31) == 0) sred[tid >> 5] = (double)sse;
    __syncthreads();
    if (tid == 0) {
        double s = 0.0;
#pragma unroll
        for (int w = 0; w < 8; w++) s += sred[w];
        atomicAdd(&g_sse, s);
    }
}

// ---------------------------------------------------------------------------
__global__ void vq_final(float* __restrict__ out, int nd, int n) {
    int t = threadIdx.x;  // 512
    __shared__ double ssum;
    __shared__ float red[16];

    int h = g_hist[t];
    g_hist[t] = 0;                         // reset for next replay
    if (t == 0) { ssum = g_sse; g_sse = 0.0; }

    float p = (float)h / (float)n;
    float e = p * logf(p + 1e-10f);
#pragma unroll
    for (int o = 16; o > 0; o >>= 1)
        e += __shfl_xor_sync(0xFFFFFFFFu, e, o);
    if ((t & 31) == 0) red[t >> 5] = e;
    __syncthreads();
    if (t < 16) {
        float v = red[t];
#pragma unroll
        for (int o = 8; o > 0; o >>= 1)
            v += __shfl_xor_sync(0xFFFFu, v, o);
        if (t == 0) {
            out[1 + nd] = expf(-v);
            float m = (float)(ssum / (double)nd);
            out[0] = m + 0.25f * m;
        }
    }
}

// ---------------------------------------------------------------------------
extern "C" void kernel_launch(void* const* d_in, const int* in_sizes, int n_in,
                              void* d_out, int out_size) {
    const float* x  = (const float*)d_in[0];
    const float* cb = (const float*)d_in[1];
    float* out = (float*)d_out;

    int nd = in_sizes[0];   // 4194304
    int n  = nd / D_DIM;    // 65536

    cudaFuncSetAttribute(vq_main, cudaFuncAttributeMaxDynamicSharedMemorySize,
                         SMEM_SZ);

    vq_prep<<<64, 256>>>(cb);
    vq_main<<<TILES, TPB, SMEM_SZ>>>(x, cb, out + 1, out + 2 + nd);
    vq_final<<<1, K_CODES>>>(out, nd, n);
}

// round 14
// speedup vs baseline: 3.3769x; 1.4769x over previous
#include <cuda_runtime.h>
#include <cuda_bf16.h>
#include <cuda_fp16.h>
#include <cstdint>
#include <math.h>

// VectorQuantizer N=65536, D=64, K=512.
// R14: R11 two-phase HMMA screen, but phase 2 only visits the warp-union of
// tiles flagged by a per-lane f16 tile-min map (built branch-free in phase 1).
// Rescore volume stays at R11's ~300 exact scores/CTA.
// d_out: [0]=loss, [1..ND]=q_st, [1+ND]=ppl, [2+ND..)=idx.

#define D_DIM   64
#define K_CODES 512
#define M_TILE  128
#define TILES   512          // 65536 / 128
#define TPB     256
#define EPS     5e-3f        // >= 2x two-sided worst-case bf16 screen error
#define MAXC    24

typedef unsigned int u32;
typedef unsigned long long u64;

__device__ __nv_bfloat16 g_cbb[K_CODES * D_DIM];  // bf16 codebook
__device__ float  g_cnorm[K_CODES];
__device__ int    g_hist[K_CODES];                // reset by vq_final
__device__ double g_sse;                          // reset by vq_final

__device__ __forceinline__ u32 smem_u32(const void* p) {
    u32 a;
    asm("{ .reg .u64 t; cvta.to.shared.u64 t, %1; cvt.u32.u64 %0, t; }"
        : "=r"(a) : "l"(p));
    return a;
}
__device__ __forceinline__ u32 sw128(u32 b) { return b ^ ((b >> 3) & 0x70); }

__device__ __forceinline__ void ldsm_x4(u32& r0, u32& r1, u32& r2, u32& r3, u32 a) {
    asm volatile("ldmatrix.sync.aligned.m8n8.x4.shared.b16 {%0,%1,%2,%3}, [%4];"
                 : "=r"(r0), "=r"(r1), "=r"(r2), "=r"(r3) : "r"(a));
}
__device__ __forceinline__ void ldsm_x2(u32& r0, u32& r1, u32 a) {
    asm volatile("ldmatrix.sync.aligned.m8n8.x2.shared.b16 {%0,%1}, [%2];"
                 : "=r"(r0), "=r"(r1) : "r"(a));
}
__device__ __forceinline__ void mma16816(float& c0, float& c1, float& c2, float& c3,
                                         u32 a0, u32 a1, u32 a2, u32 a3,
                                         u32 b0, u32 b1) {
    asm volatile(
        "mma.sync.aligned.m16n8k16.row.col.f32.bf16.bf16.f32 "
        "{%0,%1,%2,%3}, {%4,%5,%6,%7}, {%8,%9}, {%0,%1,%2,%3};"
        : "+f"(c0), "+f"(c1), "+f"(c2), "+f"(c3)
        : "r"(a0), "r"(a1), "r"(a2), "r"(a3), "r"(b0), "r"(b1));
}

// ---- smem layout (bytes), ~98 KB -> 2 CTAs/SM ----
#define SM_A    0                        // 128 rows * 128B bf16 (SW128) = 16384
#define SM_B    16384                    // 512 rows * 128B bf16 (SW128) = 65536
#define SM_CN   81920                    // 512 f32 = 2048
#define SM_AN   83968                    // 128 f32 = 512
#define SM_AND  84480                    // 256 double (half norms) = 2048
#define SM_CNT  86528                    // 128 int = 512
#define SM_CAND 87040                    // 128*24 int = 12288
#define SM_KEY  99328                    // 128 u64 = 1024
#define SM_RED  100352                   // 8 double = 64
#define SMEM_SZ 100416

// ---------------------------------------------------------------------------
__global__ void vq_prep(const float* __restrict__ cb) {
    int gt = blockIdx.x * 256 + threadIdx.x;
    int w = gt >> 5, lane = gt & 31;                 // w = code 0..511
    const float* c = cb + w * D_DIM;
    float v0 = c[lane], v1 = c[lane + 32];
    g_cbb[w * D_DIM + lane]      = __float2bfloat16(v0);
    g_cbb[w * D_DIM + lane + 32] = __float2bfloat16(v1);
    double s = (double)__fmul_rn(v0, v0) + (double)__fmul_rn(v1, v1);
#pragma unroll
    for (int o = 16; o > 0; o >>= 1)
        s += __shfl_xor_sync(0xFFFFFFFFu, s, o);
    if (lane == 0) g_cnorm[w] = (float)s;
}

// Exact fp32 score s = fl( fl(A - 2*dot) + C ), 4-chain fp32 dot.
__device__ __forceinline__ float exact_score(const float* __restrict__ cb,
                                             const float4* __restrict__ xr,
                                             float A, float C, int k) {
    const float4* cr = (const float4*)(cb + k * D_DIM);
    float a0 = 0.f, a1 = 0.f, a2 = 0.f, a3 = 0.f;
#pragma unroll
    for (int j = 0; j < D_DIM / 4; j++) {
        float4 cv = cr[j], xv = xr[j];
        a0 = __fmaf_rn(xv.x, cv.x, a0);
        a1 = __fmaf_rn(xv.y, cv.y, a1);
        a2 = __fmaf_rn(xv.z, cv.z, a2);
        a3 = __fmaf_rn(xv.w, cv.w, a3);
    }
    float dot = (a0 + a1) + (a2 + a3);
    return __fadd_rn(__fmaf_rn(-2.f, dot, A), C);
}

// ---------------------------------------------------------------------------
__global__ __launch_bounds__(TPB, 2)
void vq_main(const float* __restrict__ x, const float* __restrict__ cb,
             float* __restrict__ outq, float* __restrict__ outidx) {
    extern __shared__ char smem[];
    const u32 sb  = smem_u32(smem);
    const int tid = threadIdx.x;
    const int lane = tid & 31;
    const int wrow = (tid >> 5) * 16;               // warp's first local row
    const int row  = tid & 127;                     // pair row
    const int half = tid >> 7;                      // 0: cols 0-31, 1: 32-63

    float*  scn  = (float*)(smem + SM_CN);
    float*  san  = (float*)(smem + SM_AN);
    double* sand = (double*)(smem + SM_AND);
    int*    scnt = (int*)(smem + SM_CNT);
    int*    scand= (int*)(smem + SM_CAND);
    u64*    skey = (u64*)(smem + SM_KEY);
    double* sred = (double*)(smem + SM_RED);

    // B: bf16 codebook -> smem SW128 (2 rows/thread, 8x uint4 each)
    {
#pragma unroll
        for (int rr = 0; rr < 2; rr++) {
            int r = tid * 2 + rr;
            const uint4* src = (const uint4*)(g_cbb + r * D_DIM);
#pragma unroll
            for (int j = 0; j < 8; j++)
                *(uint4*)(smem + SM_B + sw128(r * 128 + j * 16)) = src[j];
        }
    }
    scn[tid]       = g_cnorm[tid];
    scn[tid + 256] = g_cnorm[tid + 256];
    if (tid < M_TILE) { scnt[tid] = 0; skey[tid] = ~0ull; }

    // A: convert x half-rows to bf16 SW128 + half norms (all 256 threads)
    {
        const float4* gx = (const float4*)(x +
            ((size_t)blockIdx.x * M_TILE + row) * D_DIM + half * 32);
        double sa = 0.0;
#pragma unroll
        for (int j = 0; j < 8; j++) {
            float4 v = gx[j];
            sa += (double)__fmul_rn(v.x, v.x); sa += (double)__fmul_rn(v.y, v.y);
            sa += (double)__fmul_rn(v.z, v.z); sa += (double)__fmul_rn(v.w, v.w);
            __nv_bfloat162 p0 = __floats2bfloat162_rn(v.x, v.y);
            __nv_bfloat162 p1 = __floats2bfloat162_rn(v.z, v.w);
            u32 base = (u32)row * 128 + half * 64 + j * 8;
            *(u32*)(smem + SM_A + sw128(base))     = *(u32*)&p0;
            *(u32*)(smem + SM_A + sw128(base + 4)) = *(u32*)&p1;
        }
        sand[tid] = sa;
    }
    __syncthreads();
    if (tid < M_TILE) san[tid] = (float)(sand[tid] + sand[tid + 128]);
    __syncthreads();

    // ---- screening: each warp handles rows [wrow, wrow+16) x 512 codes ----
    {
        u32 af[4][4];
        {
            int r  = (lane & 7) + ((lane & 8) ? 8 : 0);
            int hh = (lane >> 4) & 1;
            u32 abase = (u32)(wrow + r) * 128 + hh * 16;
#pragma unroll
            for (int ks = 0; ks < 4; ks++)
                ldsm_x4(af[ks][0], af[ks][1], af[ks][2], af[ks][3],
                        sb + SM_A + sw128(abase + ks * 32));
        }
        const u32 bbase = (u32)(lane & 7) * 128 + ((lane >> 3) & 1) * 16;
        const int r0 = wrow + (lane >> 2);
        const int nlo = (lane & 3) * 2;

        // Phase 1: row minima + branch-free per-tile f16 minima (regs)
        u32 tmins[32];                              // 64 tiles, 2 f16 per u32
        float tb0 = 3.4e38f, tb1 = 3.4e38f;
#pragma unroll
        for (int tp = 0; tp < 32; tp++) {
            u32 hpack = 0;
#pragma unroll
            for (int sub = 0; sub < 2; sub++) {
                const int tile = 2 * tp + sub;
                float c0 = 0.f, c1 = 0.f, c2 = 0.f, c3 = 0.f;
                u32 tb_off = (u32)tile * 8 * 128;
#pragma unroll
                for (int ks = 0; ks < 4; ks++) {
                    u32 b0, b1;
                    ldsm_x2(b0, b1, sb + SM_B + sw128(tb_off + bbase + ks * 32));
                    mma16816(c0, c1, c2, c3,
                             af[ks][0], af[ks][1], af[ks][2], af[ks][3], b0, b1);
                }
                int k0 = tile * 8 + nlo;
                float cn0 = scn[k0], cn1 = scn[k0 + 1];
                float t00 = __fmaf_rn(-2.f, c0, cn0);
                float t01 = __fmaf_rn(-2.f, c1, cn1);
                float t10 = __fmaf_rn(-2.f, c2, cn0);
                float t11 = __fmaf_rn(-2.f, c3, cn1);
                float m0 = fminf(t00, t01), m1 = fminf(t10, t11);
                tb0 = fminf(tb0, m0);
                tb1 = fminf(tb1, m1);
                u32 h = (u32)__half_as_ushort(__float2half_rd(fminf(m0, m1)));
                hpack |= h << (16 * sub);
            }
            tmins[tp] = hpack;
        }
        // True row minima via quad reduce -> thresholds
        tb0 = fminf(tb0, __shfl_xor_sync(0xFFFFFFFFu, tb0, 1));
        tb0 = fminf(tb0, __shfl_xor_sync(0xFFFFFFFFu, tb0, 2));
        tb1 = fminf(tb1, __shfl_xor_sync(0xFFFFFFFFu, tb1, 1));
        tb1 = fminf(tb1, __shfl_xor_sync(0xFFFFFFFFu, tb1, 2));
        const float thr0 = tb0 + EPS, thr1 = tb1 + EPS;
        const float thrm = fmaxf(thr0, thr1);

        // Per-lane flagged-tile mask (branch-free). f16_rd(min) <= min and
        // thr_row <= thrm, so every tile with a sub-threshold score is in it.
        u64 mask = 0;
#pragma unroll
        for (int tp = 0; tp < 32; tp++) {
            u32 pk = tmins[tp];
            float lo = __half2float(__ushort_as_half((unsigned short)(pk & 0xFFFF)));
            float hi = __half2float(__ushort_as_half((unsigned short)(pk >> 16)));
            mask |= ((u64)(lo < thrm) << (2 * tp)) |
                    ((u64)(hi < thrm) << (2 * tp + 1));
        }
        // Warp union (mask is then identical in all lanes -> uniform loop)
#pragma unroll
        for (int o = 16; o > 0; o >>= 1)
            mask |= __shfl_xor_sync(0xFFFFFFFFu, mask, o);

        // Phase 2: MMA only on union tiles; push candidates vs thresholds
        while (mask) {
            int tile = __ffsll((long long)mask) - 1;
            mask &= mask - 1;
            float c0 = 0.f, c1 = 0.f, c2 = 0.f, c3 = 0.f;
            u32 tb_off = (u32)tile * 8 * 128;
#pragma unroll
            for (int ks = 0; ks < 4; ks++) {
                u32 b0, b1;
                ldsm_x2(b0, b1, sb + SM_B + sw128(tb_off + bbase + ks * 32));
                mma16816(c0, c1, c2, c3,
                         af[ks][0], af[ks][1], af[ks][2], af[ks][3], b0, b1);
            }
            int k0 = tile * 8 + nlo;
            float cn0 = scn[k0], cn1 = scn[k0 + 1];
            float t00 = __fmaf_rn(-2.f, c0, cn0);
            float t01 = __fmaf_rn(-2.f, c1, cn1);
            float t10 = __fmaf_rn(-2.f, c2, cn0);
            float t11 = __fmaf_rn(-2.f, c3, cn1);
            if (t00 < thr0) {
                int p = atomicAdd(&scnt[r0], 1);
                if (p < MAXC) scand[r0 * MAXC + p] = k0;
            }
            if (t01 < thr0) {
                int p = atomicAdd(&scnt[r0], 1);
                if (p < MAXC) scand[r0 * MAXC + p] = k0 + 1;
            }
            if (t10 < thr1) {
                int p = atomicAdd(&scnt[r0 + 8], 1);
                if (p < MAXC) scand[(r0 + 8) * MAXC + p] = k0;
            }
            if (t11 < thr1) {
                int p = atomicAdd(&scnt[r0 + 8], 1);
                if (p < MAXC) scand[(r0 + 8) * MAXC + p] = k0 + 1;
            }
        }
    }
    __syncthreads();

    // ---- exact rescore: pair-split candidates, u64-key argmin merge ----
    const int vid = blockIdx.x * M_TILE + row;
    const float4* xr = (const float4*)(x + (size_t)vid * D_DIM);
    {
        const float A = san[row];
        int nc = scnt[row];
        if (nc > MAXC) {                 // overflow: split full exact scan
            for (int k = half; k < K_CODES; k += 2) {
                float s = exact_score(cb, xr, A, scn[k], k);
                atomicMin(&skey[row], ((u64)__float_as_uint(s) << 32) | (u32)k);
            }
        } else {
            const int* cl = scand + row * MAXC;
            for (int i = half; i < nc; i += 2) {
                int k = cl[i];
                float s = exact_score(cb, xr, A, scn[k], k);
                // s > 0 (dist^2 ~ 64): float-bits order == value order.
                atomicMin(&skey[row], ((u64)__float_as_uint(s) << 32) | (u32)k);
            }
        }
    }
    __syncthreads();

    const int bi = (int)(u32)skey[row];
    if (half == 0) {
        outidx[vid] = (float)bi;
        atomicAdd(&g_hist[bi], 1);
    }

    // ---- epilogue: 2 threads/row, 32 floats each ----
    // quantized_st = x + (q - x); SSE of (q - x)^2.
    // outq is d_out+1 (odd float offset): scalar 32-bit stores only.
    float sse = 0.f;
    {
        const float4* qr = (const float4*)(cb + bi * D_DIM) + half * 8;
        const float4* xh = xr + half * 8;
        float* o = outq + (size_t)vid * D_DIM + half * 32;
#pragma unroll
        for (int j = 0; j < 8; j++) {
            float4 qv = qr[j], xv = xh[j];
            float d0 = __fadd_rn(qv.x, -xv.x), d1 = __fadd_rn(qv.y, -xv.y);
            float d2 = __fadd_rn(qv.z, -xv.z), d3 = __fadd_rn(qv.w, -xv.w);
            sse += d0 * d0 + d1 * d1 + d2 * d2 + d3 * d3;
            o[4 * j]     = __fadd_rn(xv.x, d0);
            o[4 * j + 1] = __fadd_rn(xv.y, d1);
            o[4 * j + 2] = __fadd_rn(xv.z, d2);
            o[4 * j + 3] = __fadd_rn(xv.w, d3);
        }
    }

    // Block-reduce SSE -> one double atomic per CTA
#pragma unroll
    for (int o = 16; o > 0; o >>= 1)
        sse += __shfl_xor_sync(0xFFFFFFFFu, sse, o);
    if ((tid & 31) == 0) sred[tid >> 5] = (double)sse;
    __syncthreads();
    if (tid == 0) {
        double s = 0.0;
#pragma unroll
        for (int w = 0; w < 8; w++) s += sred[w];
        atomicAdd(&g_sse, s);
    }
}

// ---------------------------------------------------------------------------
__global__ void vq_final(float* __restrict__ out, int nd, int n) {
    int t = threadIdx.x;  // 512
    __shared__ double ssum;
    __shared__ float red[16];

    int h = g_hist[t];
    g_hist[t] = 0;                         // reset for next replay
    if (t == 0) { ssum = g_sse; g_sse = 0.0; }

    float p = (float)h / (float)n;
    float e = p * logf(p + 1e-10f);
#pragma unroll
    for (int o = 16; o > 0; o >>= 1)
        e += __shfl_xor_sync(0xFFFFFFFFu, e, o);
    if ((t & 31) == 0) red[t >> 5] = e;
    __syncthreads();
    if (t < 16) {
        float v = red[t];
#pragma unroll
        for (int o = 8; o > 0; o >>= 1)
            v += __shfl_xor_sync(0xFFFFu, v, o);
        if (t == 0) {
            out[1 + nd] = expf(-v);
            float m = (float)(ssum / (double)nd);
            out[0] = m + 0.25f * m;
        }
    }
}

// ---------------------------------------------------------------------------
extern "C" void kernel_launch(void* const* d_in, const int* in_sizes, int n_in,
                              void* d_out, int out_size) {
    const float* x  = (const float*)d_in[0];
    const float* cb = (const float*)d_in[1];
    float* out = (float*)d_out;

    int nd = in_sizes[0];   // 4194304
    int n  = nd / D_DIM;    // 65536

    cudaFuncSetAttribute(vq_main, cudaFuncAttributeMaxDynamicSharedMemorySize,
                         SMEM_SZ);

    vq_prep<<<64, 256>>>(cb);
    vq_main<<<TILES, TPB, SMEM_SZ>>>(x, cb, out + 1, out + 2 + nd);
    vq_final<<<1, K_CODES>>>(out, nd, n);
}